// round 1
// baseline (speedup 1.0000x reference)
#include <cuda_runtime.h>

#define HIDDEN 128
#define NNODES 50000
#define NEDGES 640000

// Per-node projections: P[n][0:128] = W1a*z[n] + b1  (u),  P[n][128:256] = W1b*z[n]  (v)
__device__ float g_P[NNODES * 256];
__device__ int g_is64;

// ---------------------------------------------------------------------------
// Detect whether edge_index is int64 or int32 (JAX x64-canonicalization hazard).
// If int64: the high word of each positive index < 2^31 is exactly 0.
// If int32: values are random in [0, 50000) — odd words are nonzero whp.
// ---------------------------------------------------------------------------
__global__ void detect_kernel(const unsigned int* __restrict__ w) {
    int is64 = 1;
    for (int i = 0; i < 64; i++) {
        if (w[2 * i + 1] != 0u) { is64 = 0; break; }
    }
    g_is64 = is64;
}

// ---------------------------------------------------------------------------
// Node GEMM: P[n][j] = sum_k W1T[j][k] * z[n][k]  (+ bias1[j] for j<128)
// where W1T[j][k] = W1[(j&127)*256 + (j>>7)*128 + k]   (W1 is [128,256] row-major)
// Tiling: BM=64 nodes x BN=64 cols per block, BK=16, 256 threads, 4x4 per thread.
// ---------------------------------------------------------------------------
#define BM 64
#define BN 64
#define BK 16

__global__ __launch_bounds__(256) void node_gemm(
    const float* __restrict__ z,
    const float* __restrict__ W1,
    const float* __restrict__ bias1)
{
    __shared__ float zs[BK][BM];
    __shared__ float ws[BK][BN];

    const int j0 = blockIdx.x * BN;   // 0,64,128,192
    const int n0 = blockIdx.y * BM;
    const int tid = threadIdx.x;
    const int tx = tid & 15;          // col group
    const int ty = tid >> 4;          // row group

    float acc[4][4] = {};

    for (int k0 = 0; k0 < HIDDEN; k0 += BK) {
        // Cooperative tile loads: 1024 elements each, 4 per thread.
#pragma unroll
        for (int i = 0; i < 4; i++) {
            int e = tid + i * 256;
            int k = e >> 6;
            int m = e & 63;
            int n = n0 + m;
            zs[k][m] = (n < NNODES) ? z[n * HIDDEN + k0 + k] : 0.0f;
            int j = j0 + m;           // always < 256
            ws[k][m] = W1[(j & 127) * 256 + ((j >> 7) << 7) + k0 + k];
        }
        __syncthreads();

#pragma unroll
        for (int k = 0; k < BK; k++) {
            float4 a = *(const float4*)&zs[k][ty * 4];
            float4 b = *(const float4*)&ws[k][tx * 4];
            float av[4] = {a.x, a.y, a.z, a.w};
            float bv[4] = {b.x, b.y, b.z, b.w};
#pragma unroll
            for (int i = 0; i < 4; i++)
#pragma unroll
                for (int jj = 0; jj < 4; jj++)
                    acc[i][jj] += av[i] * bv[jj];
        }
        __syncthreads();
    }

    // Epilogue: fold bias1 into the u-half (j < 128), vectorized store.
    const int jc = j0 + tx * 4;           // 4 contiguous cols, same half (j0 multiple of 64)
    float4 bb = make_float4(0.f, 0.f, 0.f, 0.f);
    if (j0 < 128) bb = *(const float4*)&bias1[jc];

#pragma unroll
    for (int i = 0; i < 4; i++) {
        int n = n0 + ty * 4 + i;
        if (n < NNODES) {
            float4 o;
            o.x = acc[i][0] + bb.x;
            o.y = acc[i][1] + bb.y;
            o.z = acc[i][2] + bb.z;
            o.w = acc[i][3] + bb.w;
            *(float4*)&g_P[n * 256 + jc] = o;
        }
    }
}

// ---------------------------------------------------------------------------
// Edge kernel: one warp per edge.
// lane l handles cols 4l..4l+3:  acc = sum relu(u_c + v_c) * W2_c ; warp-reduce.
// (bias1 already folded into u.)
// ---------------------------------------------------------------------------
__global__ __launch_bounds__(256) void edge_kernel(
    const void* __restrict__ eidx,
    const float* __restrict__ W2,
    const float* __restrict__ bias2,
    float* __restrict__ out)
{
    const int warp = (int)((blockIdx.x * blockDim.x + threadIdx.x) >> 5);
    const int lane = threadIdx.x & 31;
    if (warp >= NEDGES) return;

    int s, d;
    if (g_is64) {
        const long long* p = (const long long*)eidx;
        s = (int)p[warp];
        d = (int)p[NEDGES + warp];
    } else {
        const int* p = (const int*)eidx;
        s = p[warp];
        d = p[NEDGES + warp];
    }

    float4 u = *(const float4*)&g_P[s * 256 + lane * 4];
    float4 v = *(const float4*)&g_P[d * 256 + 128 + lane * 4];
    float4 w = ((const float4*)W2)[lane];

    float acc;
    acc  = fmaxf(u.x + v.x, 0.0f) * w.x;
    acc += fmaxf(u.y + v.y, 0.0f) * w.y;
    acc += fmaxf(u.z + v.z, 0.0f) * w.z;
    acc += fmaxf(u.w + v.w, 0.0f) * w.w;

#pragma unroll
    for (int o = 16; o; o >>= 1)
        acc += __shfl_xor_sync(0xffffffffu, acc, o);

    if (lane == 0) out[warp] = acc + bias2[0];
}

// ---------------------------------------------------------------------------
// Inputs (metadata order): z, W1, bias1, W2, bias2, edge_index
// ---------------------------------------------------------------------------
extern "C" void kernel_launch(void* const* d_in, const int* in_sizes, int n_in,
                              void* d_out, int out_size)
{
    const float* z  = (const float*)d_in[0];
    const float* W1 = (const float*)d_in[1];
    const float* b1 = (const float*)d_in[2];
    const float* W2 = (const float*)d_in[3];
    const float* b2 = (const float*)d_in[4];
    const void*  ei = d_in[5];

    detect_kernel<<<1, 1>>>((const unsigned int*)ei);

    dim3 grid(256 / BN, (NNODES + BM - 1) / BM);   // 4 x 782
    node_gemm<<<grid, 256>>>(z, W1, b1);

    edge_kernel<<<NEDGES / 8, 256>>>(ei, W2, b2, (float*)d_out);
}

// round 2
// speedup vs baseline: 1.7615x; 1.7615x over previous
#include <cuda_runtime.h>

#define HIDDEN 128
#define NNODES 50000
#define NEDGES 640000

// Per-node projections: P[n][0:128] = W1a*z[n] + b1  (u),  P[n][128:256] = W1b*z[n]  (v)
__device__ float g_P[NNODES * 256];
__device__ int g_is64;

// ---------------------------------------------------------------------------
// Packed f32x2 helpers (sm_103a FFMA2 — only reachable via PTX fma.rn.f32x2)
// ---------------------------------------------------------------------------
__device__ __forceinline__ unsigned long long pack2(float lo, float hi) {
    unsigned long long r;
    asm("mov.b64 %0, {%1, %2};" : "=l"(r) : "f"(lo), "f"(hi));
    return r;
}
__device__ __forceinline__ void ffma2(unsigned long long& d,
                                      unsigned long long a,
                                      unsigned long long b) {
    asm("fma.rn.f32x2 %0, %1, %2, %0;" : "+l"(d) : "l"(a), "l"(b));
}
__device__ __forceinline__ float2 unpack2(unsigned long long v) {
    float2 r;
    asm("mov.b64 {%0, %1}, %2;" : "=f"(r.x), "=f"(r.y) : "l"(v));
    return r;
}

// ---------------------------------------------------------------------------
// Detect int64 vs int32 edge_index (JAX x64-canonicalization hazard).
// int64: high words of first 32 entries are all 0. int32: random values whp.
// ---------------------------------------------------------------------------
__global__ void detect_kernel(const unsigned int* __restrict__ w) {
    int lane = threadIdx.x;
    unsigned int v = w[2 * lane + 1];
    unsigned int bal = __ballot_sync(0xffffffffu, v != 0u);
    if (lane == 0) g_is64 = (bal == 0u) ? 1 : 0;
}

// ---------------------------------------------------------------------------
// Node GEMM: P[n][j] = sum_k W1T[j][k] * z[n][k]  (+ bias1[j] for j<128)
// W1T[j][k] = W1[(j&127)*256 + (j>=128 ? 128 : 0) + k]   (W1 is [128,256] row-major)
// Tiling: 128 nodes x 128 cols per block, BK=8, 256 threads, 8x8 micro-tile,
// inner product via packed fma.rn.f32x2 (2 FMA/instr -> 128 FMA/cyc/SM).
// ---------------------------------------------------------------------------
__global__ __launch_bounds__(256) void node_gemm(
    const float* __restrict__ z,
    const float* __restrict__ W1,
    const float* __restrict__ bias1)
{
    __shared__ float zs[8][128];
    __shared__ float ws[8][128];

    const int j0 = blockIdx.x * 128;     // 0 (u-half) or 128 (v-half)
    const int n0 = blockIdx.y * 128;
    const int tid = threadIdx.x;
    const int tx = tid & 15;             // col micro-tile: cols j0 + tx*8 .. +7
    const int ty = tid >> 4;             // row micro-tile: nodes n0 + ty*8 .. +7

    // Cooperative load indices: 1024 floats per tile per operand = 1 float4/thread.
    const int ln = tid >> 1;             // 0..127 row within tile
    const int lk = (tid & 1) * 4;        // 0 or 4

    const bool zrow_ok = (n0 + ln) < NNODES;
    const float* zg = z + (size_t)(n0 + ln) * HIDDEN + lk;
    const float* wg = W1 + (size_t)ln * 256 + j0 + lk;   // row (j-j0)=ln, col j0+k

    unsigned long long acc[8][4];
#pragma unroll
    for (int i = 0; i < 8; i++)
#pragma unroll
        for (int jp = 0; jp < 4; jp++) acc[i][jp] = 0ull;

    // Prefetch tile 0 into registers.
    float4 zr = zrow_ok ? *(const float4*)zg : make_float4(0.f, 0.f, 0.f, 0.f);
    float4 wr = *(const float4*)wg;

#pragma unroll 1
    for (int kt = 0; kt < HIDDEN / 8; kt++) {
        // Stage current tile to smem (transposed to [k][row]).
        zs[lk + 0][ln] = zr.x; zs[lk + 1][ln] = zr.y;
        zs[lk + 2][ln] = zr.z; zs[lk + 3][ln] = zr.w;
        ws[lk + 0][ln] = wr.x; ws[lk + 1][ln] = wr.y;
        ws[lk + 2][ln] = wr.z; ws[lk + 3][ln] = wr.w;
        __syncthreads();

        // Prefetch next tile while computing this one.
        if (kt + 1 < HIDDEN / 8) {
            zr = zrow_ok ? *(const float4*)(zg + (kt + 1) * 8)
                         : make_float4(0.f, 0.f, 0.f, 0.f);
            wr = *(const float4*)(wg + (kt + 1) * 8);
        }

#pragma unroll
        for (int k = 0; k < 8; k++) {
            float4 a0 = *(const float4*)&zs[k][ty * 8];
            float4 a1 = *(const float4*)&zs[k][ty * 8 + 4];
            float4 b0 = *(const float4*)&ws[k][tx * 8];
            float4 b1 = *(const float4*)&ws[k][tx * 8 + 4];
            // b pairs come from adjacent float4 lanes (register pairs, near-free).
            unsigned long long bp[4] = {
                pack2(b0.x, b0.y), pack2(b0.z, b0.w),
                pack2(b1.x, b1.y), pack2(b1.z, b1.w)
            };
            float av[8] = {a0.x, a0.y, a0.z, a0.w, a1.x, a1.y, a1.z, a1.w};
#pragma unroll
            for (int i = 0; i < 8; i++) {
                unsigned long long ap = pack2(av[i], av[i]);   // broadcast dup
#pragma unroll
                for (int jp = 0; jp < 4; jp++) ffma2(acc[i][jp], ap, bp[jp]);
            }
        }
        __syncthreads();
    }

    // Epilogue: fold bias1 into the u-half (j0==0), vectorized stores.
    float bv[8];
#pragma unroll
    for (int q = 0; q < 8; q++) bv[q] = 0.f;
    if (j0 == 0) {
        float4 t0 = *(const float4*)(bias1 + tx * 8);
        float4 t1 = *(const float4*)(bias1 + tx * 8 + 4);
        bv[0] = t0.x; bv[1] = t0.y; bv[2] = t0.z; bv[3] = t0.w;
        bv[4] = t1.x; bv[5] = t1.y; bv[6] = t1.z; bv[7] = t1.w;
    }

#pragma unroll
    for (int i = 0; i < 8; i++) {
        int n = n0 + ty * 8 + i;
        if (n < NNODES) {
            float2 p0 = unpack2(acc[i][0]);
            float2 p1 = unpack2(acc[i][1]);
            float2 p2 = unpack2(acc[i][2]);
            float2 p3 = unpack2(acc[i][3]);
            float4 o0 = make_float4(p0.x + bv[0], p0.y + bv[1], p1.x + bv[2], p1.y + bv[3]);
            float4 o1 = make_float4(p2.x + bv[4], p2.y + bv[5], p3.x + bv[6], p3.y + bv[7]);
            float* dst = &g_P[(size_t)n * 256 + j0 + tx * 8];
            *(float4*)dst = o0;
            *(float4*)(dst + 4) = o1;
        }
    }
}

// ---------------------------------------------------------------------------
// Edge kernel: one warp per edge (L2-bandwidth bound, ~1KB/edge from L2).
// lane l handles cols 4l..4l+3: acc = sum relu(u_c + v_c) * W2_c ; warp-reduce.
// (bias1 already folded into u.)
// ---------------------------------------------------------------------------
__global__ __launch_bounds__(256) void edge_kernel(
    const void* __restrict__ eidx,
    const float* __restrict__ W2,
    const float* __restrict__ bias2,
    float* __restrict__ out)
{
    const int warp = (int)((blockIdx.x * blockDim.x + threadIdx.x) >> 5);
    const int lane = threadIdx.x & 31;
    if (warp >= NEDGES) return;

    int s, d;
    if (g_is64) {
        const long long* p = (const long long*)eidx;
        s = (int)p[warp];
        d = (int)p[NEDGES + warp];
    } else {
        const int* p = (const int*)eidx;
        s = p[warp];
        d = p[NEDGES + warp];
    }

    float4 u = *(const float4*)&g_P[(size_t)s * 256 + lane * 4];
    float4 v = *(const float4*)&g_P[(size_t)d * 256 + 128 + lane * 4];
    float4 w = ((const float4*)W2)[lane];

    float acc;
    acc  = fmaxf(u.x + v.x, 0.0f) * w.x;
    acc += fmaxf(u.y + v.y, 0.0f) * w.y;
    acc += fmaxf(u.z + v.z, 0.0f) * w.z;
    acc += fmaxf(u.w + v.w, 0.0f) * w.w;

#pragma unroll
    for (int o = 16; o; o >>= 1)
        acc += __shfl_xor_sync(0xffffffffu, acc, o);

    if (lane == 0) out[warp] = acc + bias2[0];
}

// ---------------------------------------------------------------------------
// Inputs (metadata order): z, W1, bias1, W2, bias2, edge_index
// ---------------------------------------------------------------------------
extern "C" void kernel_launch(void* const* d_in, const int* in_sizes, int n_in,
                              void* d_out, int out_size)
{
    const float* z  = (const float*)d_in[0];
    const float* W1 = (const float*)d_in[1];
    const float* b1 = (const float*)d_in[2];
    const float* W2 = (const float*)d_in[3];
    const float* b2 = (const float*)d_in[4];
    const void*  ei = d_in[5];

    detect_kernel<<<1, 32>>>((const unsigned int*)ei);

    dim3 grid(2, (NNODES + 127) / 128);   // 2 x 391
    node_gemm<<<grid, 256>>>(z, W1, b1);

    edge_kernel<<<NEDGES / 8, 256>>>(ei, W2, b2, (float*)d_out);
}